// round 16
// baseline (speedup 1.0000x reference)
#include <cuda_runtime.h>
#include <cuda_bf16.h>
#include <math.h>
#include <stdint.h>

#define NN 50000
#define EE 640000
#define DD 128
#define EDIM 64
#define HH 4
#define HC 128
#define EN (EE+NN)

#define WOFF_WE 0
#define WOFF_WL 8192
#define WOFF_WR 24576
#define WOFF_W1 40960
#define WOFF_W2 73728
#define WTOTAL  106496
#define WPAIRS  (WTOTAL/2)

#define SCAN_NBLK ((NN + 255)/256)   // 196
#define EL_NTILES ((EN + 127)/128)   // 5391
#define EL_GRID 296                  // 2 CTAs per SM

// ---------------- scratch (device globals; no allocation) ----------------
__device__ float g_xl[NN*HC];
__device__ float g_xr[NN*HC];
__device__ float g_loop[NN*EDIM];
__device__ float g_h[NN*DD];
__device__ float g_mid[NN*2*DD];
__device__ uint32_t g_w16h[WPAIRS];
__device__ uint32_t g_w16l[WPAIRS];
__device__ int   g_cnt[NN];
__device__ int   g_cur[NN];
__device__ int   g_off[NN+1];
__device__ int   g_bsum[SCAN_NBLK];
__device__ int   g_boff[SCAN_NBLK];
__device__ int   g_srow[EE];
__device__ int   g_ssrc[EE];

// device-global router: device globals must NEVER be passed as kernel args from host
template<int B> __device__ __forceinline__ float* bufsel(const float* ext){
    if constexpr (B==0) return const_cast<float*>(ext);
    else if constexpr (B==6) return g_h;
    else return g_mid;
}

// ---------------- bf16 split helpers ----------------
__device__ __forceinline__ uint32_t bf16x2_of(float lo_elem, float hi_elem){
    uint32_t r; asm("cvt.rn.bf16x2.f32 %0, %1, %2;" : "=r"(r) : "f"(hi_elem), "f"(lo_elem)); return r;
}
__device__ __forceinline__ float2 bf16x2_back(uint32_t p){
    return make_float2(__uint_as_float(p << 16), __uint_as_float(p & 0xffff0000u));
}
__device__ __forceinline__ void split2(float x, float y, uint32_t& h, uint32_t& l){
    h = bf16x2_of(x, y);
    float2 hb = bf16x2_back(h);
    l = bf16x2_of(x - hb.x, y - hb.y);
}

__device__ __forceinline__ uint32_t smem_u32(const void* p){
    uint32_t a;
    asm("{ .reg .u64 t; cvta.to.shared.u64 t, %1; cvt.u32.u64 %0, t; }" : "=r"(a) : "l"(p));
    return a;
}

__device__ __forceinline__ void ldsm_x4(uint32_t* r, uint32_t addr){
    asm volatile("ldmatrix.sync.aligned.m8n8.x4.shared.b16 {%0,%1,%2,%3}, [%4];"
        : "=r"(r[0]), "=r"(r[1]), "=r"(r[2]), "=r"(r[3]) : "r"(addr));
}
__device__ __forceinline__ void mma16816(float* c, const uint32_t* a, uint32_t b0, uint32_t b1){
    asm volatile("mma.sync.aligned.m16n8k16.row.col.f32.bf16.bf16.f32 "
        "{%0,%1,%2,%3}, {%4,%5,%6,%7}, {%8,%9}, {%0,%1,%2,%3};"
        : "+f"(c[0]), "+f"(c[1]), "+f"(c[2]), "+f"(c[3])
        : "r"(a[0]), "r"(a[1]), "r"(a[2]), "r"(a[3]), "r"(b0), "r"(b1));
}

#define EL_STRIDE 72
#define EL_BUF (128*EL_STRIDE*2)          // 18432 B per buffer
#define EL_SMEM_BYTES (4*EL_BUF)          // 73728 B
#define WA_BUF (64*EL_STRIDE*2)           // 9216
#define WB_BUF (256*EL_STRIDE*2)          // 36864
#define WIDE_SMEM_BYTES (2*WA_BUF + 2*WB_BUF)  // 92160

// ---------------- weight pre-split + zero counters ----------------
__global__ void k_wsplit(const float* __restrict__ We, const float* __restrict__ Wl,
                         const float* __restrict__ Wr, const float* __restrict__ W1,
                         const float* __restrict__ W2){
    int p = blockIdx.x*blockDim.x + threadIdx.x;
    if (p < NN) g_cnt[p] = 0;
    if (p >= WPAIRS) return;
    int e = p*2;
    const float* src; int base;
    if (e < WOFF_WL)      { src = We; base = WOFF_WE; }
    else if (e < WOFF_WR) { src = Wl; base = WOFF_WL; }
    else if (e < WOFF_W1) { src = Wr; base = WOFF_WR; }
    else if (e < WOFF_W2) { src = W1; base = WOFF_W1; }
    else                  { src = W2; base = WOFF_W2; }
    float2 v = *(const float2*)&src[e - base];
    uint32_t h, l; split2(v.x, v.y, h, l);
    g_w16h[p] = h; g_w16l[p] = l;
}

// ---------------- init: ei_sl output + degree count ----------------
__global__ void k_init(float* __restrict__ out_ei, const int* __restrict__ ei){
    int i = blockIdx.x*blockDim.x + threadIdx.x;
    if (i < EN){
        int s = (i < EE) ? ei[i]     : (i-EE);
        int d = (i < EE) ? ei[EE+i]  : (i-EE);
        out_ei[i]    = (float)s;
        out_ei[EN+i] = (float)d;
        if (i < EE) atomicAdd(&g_cnt[d], 1);
    }
}

// 3-phase parallel scan
__global__ void k_scan1(){
    __shared__ int sp[8];
    int b = blockIdx.x, t = threadIdx.x;
    int idx = b*256 + t;
    int v = (idx < NN) ? g_cnt[idx] : 0;
    int s = v;
    #pragma unroll
    for (int o = 16; o; o >>= 1) s += __shfl_xor_sync(0xffffffffu, s, o);
    if ((t & 31) == 0) sp[t >> 5] = s;
    __syncthreads();
    if (t == 0){
        int tot = 0;
        #pragma unroll
        for (int i = 0; i < 8; i++) tot += sp[i];
        g_bsum[b] = tot;
    }
}

__global__ void k_scan2(){
    __shared__ int buf[SCAN_NBLK];
    int t = threadIdx.x;
    int v = (t < SCAN_NBLK) ? g_bsum[t] : 0;
    if (t < SCAN_NBLK) buf[t] = v;
    __syncthreads();
    for (int off = 1; off < SCAN_NBLK; off <<= 1){
        int add = (t < SCAN_NBLK && t >= off) ? buf[t-off] : 0;
        __syncthreads();
        if (t < SCAN_NBLK) buf[t] += add;
        __syncthreads();
    }
    if (t < SCAN_NBLK) g_boff[t] = buf[t] - v;
}

__global__ void k_scan3(){
    __shared__ int buf[256];
    int b = blockIdx.x, t = threadIdx.x;
    int idx = b*256 + t;
    int v = (idx < NN) ? g_cnt[idx] : 0;
    buf[t] = v;
    __syncthreads();
    for (int off = 1; off < 256; off <<= 1){
        int add = (t >= off) ? buf[t-off] : 0;
        __syncthreads();
        buf[t] += add;
        __syncthreads();
    }
    int ex = g_boff[b] + buf[t] - v;
    if (idx < NN){
        g_off[idx] = ex;
        g_cur[idx] = ex;
        if (idx == NN-1) g_off[NN] = ex + v;
    }
}

__global__ void k_scatter(const int* __restrict__ ei){
    int i = blockIdx.x*blockDim.x + threadIdx.x;
    if (i >= EE) return;
    int d = ei[EE+i];
    int p = atomicAdd(&g_cur[d], 1);
    g_srow[p] = i;
    g_ssrc[p] = ei[i];
}

// ---------------- loop attr: CSR gather mean (warp per node, float2) ----------------
__global__ void k_loopattr(const float* __restrict__ ea){
    int t = blockIdx.x*blockDim.x + threadIdx.x;
    int n = t >> 5, lane = t & 31;
    if (n >= NN) return;
    int beg = g_off[n], end = g_off[n+1];
    float a0 = 0.f, a1 = 0.f;
    #pragma unroll 2
    for (int idx = beg; idx < end; idx++){
        int row = g_srow[idx];
        float2 v = *(const float2*)&ea[(size_t)row*EDIM + lane*2];
        a0 += v.x; a1 += v.y;
    }
    float inv = 1.f / fmaxf((float)(end-beg), 1.f);
    *(float2*)&g_loop[(size_t)n*EDIM + lane*2] = make_float2(a0*inv, a1*inv);
}

// ---------------- WIDE HMMA GEMM: 64M x 256N tile, warp = 16M x 128N ----------------
// DUAL: n-half 0 -> g_xl (+bl), n-half 1 -> g_xr (+br). else C = bufsel<CBUF> (Ncol=256) +gelu.
template<int ABUF, int CBUF, bool DUAL, bool GELU>
__global__ __launch_bounds__(256) void hgemm_wide(
    const float* __restrict__ Aext, const float* __restrict__ bl,
    const float* __restrict__ br,
    int M, int K, int woff1, int woff2)
{
    const float* A = bufsel<ABUF>(Aext);
    float* C = bufsel<CBUF>(nullptr);
    extern __shared__ __align__(16) uint8_t dynsmem[];
    uint16_t* Ah = (uint16_t*)(dynsmem);
    uint16_t* Al = (uint16_t*)(dynsmem + WA_BUF);
    uint16_t* Bh = (uint16_t*)(dynsmem + 2*WA_BUF);
    uint16_t* Bl = (uint16_t*)(dynsmem + 2*WA_BUF + WB_BUF);

    int tid = threadIdx.x;
    int w = tid >> 5, lane = tid & 31;
    int row0 = blockIdx.x * 64;
    int m0 = (w & 3) * 16;
    int nh = w >> 2;

    float acc[16][4];
    #pragma unroll
    for (int j=0;j<16;j++){ acc[j][0]=0.f; acc[j][1]=0.f; acc[j][2]=0.f; acc[j][3]=0.f; }

    int arow = tid >> 2;
    int aq   = (tid & 3) * 16;
    int gm   = row0 + arow;
    int brow = tid;
    int bwo  = (brow < 128) ? (woff1 + brow*K) : (woff2 + (brow-128)*K);

    int arow_l = m0 + (lane & 15);
    int akoff  = (lane >> 4) * 8;
    uint32_t addrAh = smem_u32(Ah) + (arow_l*EL_STRIDE + akoff)*2;
    uint32_t addrAl = smem_u32(Al) + (arow_l*EL_STRIDE + akoff)*2;
    int brow_l = (lane & 7) + ((lane >> 4) << 3);
    int bkoff  = ((lane >> 3) & 1) * 8;
    uint32_t addrBh = smem_u32(Bh) + ((nh*128 + brow_l)*EL_STRIDE + bkoff)*2;
    uint32_t addrBl = smem_u32(Bl) + ((nh*128 + brow_l)*EL_STRIDE + bkoff)*2;

    for (int k0 = 0; k0 < K; k0 += 64){
        {
            const float* ap = (gm < M) ? &A[(size_t)gm*K + k0 + aq] : nullptr;
            #pragma unroll
            for (int i = 0; i < 4; i++){
                uint32_t h0, l0, h1, l1;
                if (!ap){ h0=l0=h1=l1=0u; }
                else {
                    float4 v = *(const float4*)&ap[i*4];
                    split2(v.x, v.y, h0, l0);
                    split2(v.z, v.w, h1, l1);
                }
                *(uint2*)&Ah[arow*EL_STRIDE + aq + i*4] = make_uint2(h0, h1);
                *(uint2*)&Al[arow*EL_STRIDE + aq + i*4] = make_uint2(l0, l1);
            }
        }
        {
            #pragma unroll
            for (int q = 0; q < 16; q++){
                int pidx = (bwo + k0 + q*4) >> 1;
                *(uint2*)&Bh[brow*EL_STRIDE + q*4] = *(const uint2*)&g_w16h[pidx];
                *(uint2*)&Bl[brow*EL_STRIDE + q*4] = *(const uint2*)&g_w16l[pidx];
            }
        }
        __syncthreads();
        #pragma unroll
        for (int kk = 0; kk < 4; kk++){
            uint32_t kofs = (kk*16)*2;
            uint32_t ah[4], al[4];
            ldsm_x4(ah, addrAh + kofs);
            ldsm_x4(al, addrAl + kofs);
            #pragma unroll
            for (int jj = 0; jj < 8; jj++){
                uint32_t bofs = (jj*16*EL_STRIDE)*2 + kofs;
                uint32_t bh[4], blr[4];
                ldsm_x4(bh, addrBh + bofs);
                ldsm_x4(blr, addrBl + bofs);
                mma16816(acc[2*jj],   ah, bh[0], bh[1]);
                mma16816(acc[2*jj+1], ah, bh[2], bh[3]);
                mma16816(acc[2*jj],   ah, blr[0], blr[1]);
                mma16816(acc[2*jj+1], ah, blr[2], blr[3]);
                mma16816(acc[2*jj],   al, bh[0], bh[1]);
                mma16816(acc[2*jj+1], al, bh[2], bh[3]);
            }
        }
        __syncthreads();
    }

    int qid = lane >> 2;
    int r0 = row0 + m0 + qid, r1 = r0 + 8;
    int cb2 = (lane & 3)*2;
    if (DUAL){
        float* Cd = nh ? g_xr : g_xl;
        const float* bs = nh ? br : bl;
        #pragma unroll
        for (int j = 0; j < 16; j++){
            int c = j*8 + cb2;
            float2 bv = *(const float2*)&bs[c];
            float v0 = acc[j][0] + bv.x, v1 = acc[j][1] + bv.y;
            float v2 = acc[j][2] + bv.x, v3 = acc[j][3] + bv.y;
            if (r0 < M) *(float2*)&Cd[(size_t)r0*HC + c] = make_float2(v0, v1);
            if (r1 < M) *(float2*)&Cd[(size_t)r1*HC + c] = make_float2(v2, v3);
        }
    } else {
        #pragma unroll
        for (int j = 0; j < 16; j++){
            int c = nh*128 + j*8 + cb2;
            float v0 = acc[j][0], v1 = acc[j][1], v2 = acc[j][2], v3 = acc[j][3];
            if (GELU){
                v0 = 0.5f*v0*(1.f + erff(v0*0.70710678118654752f));
                v1 = 0.5f*v1*(1.f + erff(v1*0.70710678118654752f));
                v2 = 0.5f*v2*(1.f + erff(v2*0.70710678118654752f));
                v3 = 0.5f*v3*(1.f + erff(v3*0.70710678118654752f));
            }
            if (r0 < M) *(float2*)&C[(size_t)r0*256 + c] = make_float2(v0, v1);
            if (r1 < M) *(float2*)&C[(size_t)r1*256 + c] = make_float2(v2, v3);
        }
    }
}

// ---------------- HMMA GEMM (128x128 tile) for MLP2 + fused LN2 ----------------
template<int ABUF, bool LN2>
__global__ __launch_bounds__(256) void hgemm(
    const float* __restrict__ Aext,
    const float* __restrict__ gam, const float* __restrict__ bet,
    float* __restrict__ Cext, int M, int Ncol, int K, int woff)
{
    const float* A = bufsel<ABUF>(Aext);
    float* C = Cext;   // harness pointer only
    extern __shared__ __align__(16) uint8_t dynsmem[];
    uint16_t* Ah = (uint16_t*)(dynsmem);
    uint16_t* Al = (uint16_t*)(dynsmem + EL_BUF);
    uint16_t* Bh = (uint16_t*)(dynsmem + 2*EL_BUF);
    uint16_t* Bl = (uint16_t*)(dynsmem + 3*EL_BUF);

    int tid = threadIdx.x;
    int w = tid >> 5, lane = tid & 31;
    int row0 = blockIdx.y * 128, col0 = blockIdx.x * 128;
    int m0 = w*16;

    float acc[16][4];
    #pragma unroll
    for (int j=0;j<16;j++){ acc[j][0]=0.f; acc[j][1]=0.f; acc[j][2]=0.f; acc[j][3]=0.f; }

    int crow = tid >> 1, chalf = tid & 1;
    int cb = chalf*32;
    int gm = row0 + crow;

    int arow_l = m0 + (lane & 15);
    int akoff  = (lane >> 4) * 8;
    uint32_t addrAh = smem_u32(Ah) + (arow_l*EL_STRIDE + akoff)*2;
    uint32_t addrAl = smem_u32(Al) + (arow_l*EL_STRIDE + akoff)*2;
    int brow_l = (lane & 7) + ((lane >> 4) << 3);
    int bkoff  = ((lane >> 3) & 1) * 8;
    uint32_t addrBh = smem_u32(Bh) + (brow_l*EL_STRIDE + bkoff)*2;
    uint32_t addrBl = smem_u32(Bl) + (brow_l*EL_STRIDE + bkoff)*2;

    for (int k0 = 0; k0 < K; k0 += 64){
        {
            const float* arow = (gm < M) ? &A[(size_t)gm*K + k0 + cb] : nullptr;
            #pragma unroll
            for (int q = 0; q < 8; q++){
                int col = cb + q*4;
                uint32_t h0, l0, h1, l1;
                if (!arow){ h0=l0=h1=l1=0u; }
                else {
                    float4 v = *(const float4*)&arow[q*4];
                    split2(v.x, v.y, h0, l0);
                    split2(v.z, v.w, h1, l1);
                }
                *(uint2*)&Ah[crow*EL_STRIDE + col] = make_uint2(h0, h1);
                *(uint2*)&Al[crow*EL_STRIDE + col] = make_uint2(l0, l1);
            }
        }
        {
            int belem = woff + (col0+crow)*K + k0 + cb;
            #pragma unroll
            for (int q = 0; q < 8; q++){
                int col = cb + q*4;
                int pidx = (belem + q*4) >> 1;
                *(uint2*)&Bh[crow*EL_STRIDE + col] = *(const uint2*)&g_w16h[pidx];
                *(uint2*)&Bl[crow*EL_STRIDE + col] = *(const uint2*)&g_w16l[pidx];
            }
        }
        __syncthreads();
        #pragma unroll
        for (int kk = 0; kk < 4; kk++){
            uint32_t kofs = (kk*16)*2;
            uint32_t ah[4], al[4];
            ldsm_x4(ah, addrAh + kofs);
            ldsm_x4(al, addrAl + kofs);
            #pragma unroll
            for (int jj = 0; jj < 8; jj++){
                uint32_t bofs = (jj*16*EL_STRIDE)*2 + kofs;
                uint32_t bh[4], bl[4];
                ldsm_x4(bh, addrBh + bofs);
                ldsm_x4(bl, addrBl + bofs);
                mma16816(acc[2*jj],   ah, bh[0], bh[1]);
                mma16816(acc[2*jj+1], ah, bh[2], bh[3]);
                mma16816(acc[2*jj],   ah, bl[0], bl[1]);
                mma16816(acc[2*jj+1], ah, bl[2], bl[3]);
                mma16816(acc[2*jj],   al, bh[0], bh[1]);
                mma16816(acc[2*jj+1], al, bh[2], bh[3]);
            }
        }
        __syncthreads();
    }

    int qid = lane >> 2;
    int r0 = row0 + m0 + qid, r1 = r0 + 8;
    int cbase = (lane & 3)*2;

    if (LN2){
        #pragma unroll
        for (int j = 0; j < 16; j++){
            int c = col0 + j*8 + cbase;
            if (r0 < M){
                float2 hv = *(const float2*)&g_h[(size_t)r0*Ncol + c];
                acc[j][0] += hv.x; acc[j][1] += hv.y;
            }
            if (r1 < M){
                float2 hv = *(const float2*)&g_h[(size_t)r1*Ncol + c];
                acc[j][2] += hv.x; acc[j][3] += hv.y;
            }
        }
        float s0 = 0.f, s1 = 0.f;
        #pragma unroll
        for (int j = 0; j < 16; j++){ s0 += acc[j][0] + acc[j][1]; s1 += acc[j][2] + acc[j][3]; }
        s0 += __shfl_xor_sync(0xffffffffu, s0, 1); s0 += __shfl_xor_sync(0xffffffffu, s0, 2);
        s1 += __shfl_xor_sync(0xffffffffu, s1, 1); s1 += __shfl_xor_sync(0xffffffffu, s1, 2);
        float mu0 = s0 * (1.f/128.f), mu1 = s1 * (1.f/128.f);
        float q0 = 0.f, q1 = 0.f;
        #pragma unroll
        for (int j = 0; j < 16; j++){
            float d;
            d = acc[j][0]-mu0; q0 += d*d;
            d = acc[j][1]-mu0; q0 += d*d;
            d = acc[j][2]-mu1; q1 += d*d;
            d = acc[j][3]-mu1; q1 += d*d;
        }
        q0 += __shfl_xor_sync(0xffffffffu, q0, 1); q0 += __shfl_xor_sync(0xffffffffu, q0, 2);
        q1 += __shfl_xor_sync(0xffffffffu, q1, 1); q1 += __shfl_xor_sync(0xffffffffu, q1, 2);
        float rs0 = rsqrtf(q0*(1.f/128.f) + 1e-5f);
        float rs1 = rsqrtf(q1*(1.f/128.f) + 1e-5f);
        #pragma unroll
        for (int j = 0; j < 16; j++){
            int c = col0 + j*8 + cbase;
            float2 gv = *(const float2*)&gam[c];
            float2 bv = *(const float2*)&bet[c];
            if (r0 < M)
                *(float2*)&C[(size_t)r0*Ncol + c] = make_float2(
                    (acc[j][0]-mu0)*rs0*gv.x + bv.x, (acc[j][1]-mu0)*rs0*gv.y + bv.y);
            if (r1 < M)
                *(float2*)&C[(size_t)r1*Ncol + c] = make_float2(
                    (acc[j][2]-mu1)*rs1*gv.x + bv.x, (acc[j][3]-mu1)*rs1*gv.y + bv.y);
        }
    } else {
        #pragma unroll
        for (int j = 0; j < 16; j++){
            int c = col0 + j*8 + cbase;
            if (r0 < M) *(float2*)&C[(size_t)r0*Ncol + c] = make_float2(acc[j][0], acc[j][1]);
            if (r1 < M) *(float2*)&C[(size_t)r1*Ncol + c] = make_float2(acc[j][2], acc[j][3]);
        }
    }
}

// ---------------- fused e-projection + logits: PERSISTENT, We staged once ----------------
__global__ __launch_bounds__(256) void k_elogits_hmma(
    const int* __restrict__ ei, const float* __restrict__ ea,
    const float* __restrict__ att, float* __restrict__ alpha)
{
    extern __shared__ __align__(16) uint8_t dynsmem[];
    __shared__ int s_src[128], s_dst[128];
    __shared__ float s_att[128];

    uint16_t* Ah = (uint16_t*)(dynsmem);
    uint16_t* Al = (uint16_t*)(dynsmem + EL_BUF);
    uint16_t* Bh = (uint16_t*)(dynsmem + 2*EL_BUF);
    uint16_t* Bl = (uint16_t*)(dynsmem + 3*EL_BUF);

    int tid = threadIdx.x;
    int w = tid >> 5, lane = tid & 31;

    if (tid < 128) s_att[tid] = att[tid];
    {
        int row = tid >> 1, half = tid & 1;
        int cb = half*32;
        int belem = row*EDIM + cb;
        #pragma unroll
        for (int q = 0; q < 8; q++){
            int col = cb + q*4;
            int pidx = (belem + q*4) >> 1;
            *(uint2*)&Bh[row*EL_STRIDE + col] = *(const uint2*)&g_w16h[pidx];
            *(uint2*)&Bl[row*EL_STRIDE + col] = *(const uint2*)&g_w16l[pidx];
        }
    }

    int m0 = w*16;
    int arow_l = m0 + (lane & 15);
    int akoff  = (lane >> 4) * 8;
    uint32_t addrAh = smem_u32(Ah) + (arow_l*EL_STRIDE + akoff)*2;
    uint32_t addrAl = smem_u32(Al) + (arow_l*EL_STRIDE + akoff)*2;
    int brow_l = (lane & 7) + ((lane >> 4) << 3);
    int bkoff  = ((lane >> 3) & 1) * 8;
    uint32_t addrBh = smem_u32(Bh) + (brow_l*EL_STRIDE + bkoff)*2;
    uint32_t addrBl = smem_u32(Bl) + (brow_l*EL_STRIDE + bkoff)*2;

    int crow = tid >> 1, chalf = tid & 1;
    int ccb = chalf*32;

    for (int tile = blockIdx.x; tile < EL_NTILES; tile += EL_GRID){
        int row0 = tile * 128;

        if (tid < 128){
            int e = row0 + tid;
            int s, d;
            if (e < EE){ s = ei[e]; d = ei[EE+e]; }
            else if (e < EN){ s = e-EE; d = e-EE; }
            else { s = 0; d = 0; }
            s_src[tid] = s; s_dst[tid] = d;
        }
        {
            int eg = row0 + crow;
            const float* arow = nullptr;
            bool zero = false;
            if (eg < EE)      arow = &ea[(size_t)eg*EDIM + ccb];
            else if (eg < EN) arow = &g_loop[(size_t)(eg-EE)*EDIM + ccb];
            else              zero = true;
            #pragma unroll
            for (int q = 0; q < 8; q++){
                int col = ccb + q*4;
                uint32_t h0, l0, h1, l1;
                if (zero){ h0=l0=h1=l1=0u; }
                else {
                    float4 v = *(const float4*)&arow[q*4];
                    split2(v.x, v.y, h0, l0);
                    split2(v.z, v.w, h1, l1);
                }
                *(uint2*)&Ah[crow*EL_STRIDE + col] = make_uint2(h0, h1);
                *(uint2*)&Al[crow*EL_STRIDE + col] = make_uint2(l0, l1);
            }
        }
        __syncthreads();

        float acc[16][4];
        #pragma unroll
        for (int j=0;j<16;j++){ acc[j][0]=0.f; acc[j][1]=0.f; acc[j][2]=0.f; acc[j][3]=0.f; }

        #pragma unroll
        for (int kk = 0; kk < 4; kk++){
            uint32_t kofs = (kk*16)*2;
            uint32_t ah[4], al[4];
            ldsm_x4(ah, addrAh + kofs);
            ldsm_x4(al, addrAl + kofs);
            #pragma unroll
            for (int jj = 0; jj < 8; jj++){
                uint32_t bofs = (jj*16*EL_STRIDE)*2 + kofs;
                uint32_t bh[4], bl[4];
                ldsm_x4(bh, addrBh + bofs);
                ldsm_x4(bl, addrBl + bofs);
                mma16816(acc[2*jj],   ah, bh[0], bh[1]);
                mma16816(acc[2*jj+1], ah, bh[2], bh[3]);
                mma16816(acc[2*jj],   ah, bl[0], bl[1]);
                mma16816(acc[2*jj+1], ah, bl[2], bl[3]);
                mma16816(acc[2*jj],   al, bh[0], bh[1]);
                mma16816(acc[2*jj+1], al, bh[2], bh[3]);
            }
        }

        int qid = lane >> 2;
        int r0 = m0 + qid, r1 = r0 + 8;
        int eg0 = row0 + r0, eg1 = row0 + r1;
        int sA = s_src[r0], dA = s_dst[r0];
        int sB = s_src[r1], dB = s_dst[r1];
        const float* xlA = g_xl + (size_t)sA*HC;
        const float* xrA = g_xr + (size_t)dA*HC;
        const float* xlB = g_xl + (size_t)sB*HC;
        const float* xrB = g_xr + (size_t)dB*HC;
        int cbase = (lane & 3)*2;
        float p0[4] = {0.f,0.f,0.f,0.f};
        float p1[4] = {0.f,0.f,0.f,0.f};
        #pragma unroll
        for (int j = 0; j < 16; j++){
            int c = j*8 + cbase;
            int head = j >> 2;
            float2 xl0 = *(const float2*)&xlA[c];
            float2 xr0 = *(const float2*)&xrA[c];
            float2 xl1 = *(const float2*)&xlB[c];
            float2 xr1 = *(const float2*)&xrB[c];
            float a0 = s_att[c], a1 = s_att[c+1];
            float v;
            v = acc[j][0] + xl0.x + xr0.x; v = (v>0.f)?v:0.2f*v; p0[head] += v*a0;
            v = acc[j][1] + xl0.y + xr0.y; v = (v>0.f)?v:0.2f*v; p0[head] += v*a1;
            v = acc[j][2] + xl1.x + xr1.x; v = (v>0.f)?v:0.2f*v; p1[head] += v*a0;
            v = acc[j][3] + xl1.y + xr1.y; v = (v>0.f)?v:0.2f*v; p1[head] += v*a1;
        }
        #pragma unroll
        for (int o = 1; o <= 2; o <<= 1){
            #pragma unroll
            for (int hh = 0; hh < 4; hh++){
                p0[hh] += __shfl_xor_sync(0xffffffffu, p0[hh], o);
                p1[hh] += __shfl_xor_sync(0xffffffffu, p1[hh], o);
            }
        }
        if ((lane & 3) == 0){
            if (eg0 < EN) *(float4*)&alpha[(size_t)eg0*4] = make_float4(p0[0], p0[1], p0[2], p0[3]);
            if (eg1 < EN) *(float4*)&alpha[(size_t)eg1*4] = make_float4(p1[0], p1[1], p1[2], p1[3]);
        }
        __syncthreads();
    }
}

// ---------------- online segment softmax + aggregate + residual + LN1 ----------------
__device__ __forceinline__ void online_upd(float l, float& m, float& s){
    if (l > m){ s = s*__expf(m-l) + 1.f; m = l; }
    else s += __expf(l-m);
}
__device__ __forceinline__ void online_merge(float om, float os, float& m, float& s){
    float nm = fmaxf(m, om);
    s = s*__expf(m-nm) + os*__expf(om-nm);
    m = nm;
}

__global__ void k_smagg(const float* __restrict__ x, const float* __restrict__ gbias,
                        const float* __restrict__ g1, const float* __restrict__ b1,
                        float* __restrict__ alpha)
{
    int t = blockIdx.x*blockDim.x + threadIdx.x;
    int n = t >> 5, lane = t & 31;
    if (n >= NN) return;
    int beg = g_off[n], end = g_off[n+1];
    float4* a4 = (float4*)alpha;

    float4 lsl = a4[EE+n];
    const float NEGBIG = -1e30f;
    float m0=NEGBIG,m1=NEGBIG,m2=NEGBIG,m3=NEGBIG;
    float s0=0.f,s1=0.f,s2=0.f,s3=0.f;
    for (int idx = beg + lane; idx < end; idx += 32){
        float4 l = a4[g_srow[idx]];
        online_upd(l.x, m0, s0); online_upd(l.y, m1, s1);
        online_upd(l.z, m2, s2); online_upd(l.w, m3, s3);
    }
    #pragma unroll
    for (int o = 16; o; o >>= 1){
        float om, os;
        om = __shfl_xor_sync(0xffffffffu, m0, o); os = __shfl_xor_sync(0xffffffffu, s0, o); online_merge(om, os, m0, s0);
        om = __shfl_xor_sync(0xffffffffu, m1, o); os = __shfl_xor_sync(0xffffffffu, s1, o); online_merge(om, os, m1, s1);
        om = __shfl_xor_sync(0xffffffffu, m2, o); os = __shfl_xor_sync(0xffffffffu, s2, o); online_merge(om, os, m2, s2);
        om = __shfl_xor_sync(0xffffffffu, m3, o); os = __shfl_xor_sync(0xffffffffu, s3, o); online_merge(om, os, m3, s3);
    }
    online_upd(lsl.x, m0, s0); online_upd(lsl.y, m1, s1);
    online_upd(lsl.z, m2, s2); online_upd(lsl.w, m3, s3);

    float i0 = 1.f/s0, i1 = 1.f/s1, i2 = 1.f/s2, i3 = 1.f/s3;
    float asl0 = __expf(lsl.x - m0)*i0, asl1 = __expf(lsl.y - m1)*i1;
    float asl2 = __expf(lsl.z - m2)*i2, asl3 = __expf(lsl.w - m3)*i3;
    if (lane == 0) a4[EE+n] = make_float4(asl0, asl1, asl2, asl3);
    for (int idx = beg + lane; idx < end; idx += 32){
        int row = g_srow[idx];
        float4 l = a4[row];
        a4[row] = make_float4(__expf(l.x - m0)*i0, __expf(l.y - m1)*i1,
                              __expf(l.z - m2)*i2, __expf(l.w - m3)*i3);
    }
    __syncwarp();

    int cbase = lane*4;
    int h = lane >> 3;
    float4 accv = make_float4(0.f,0.f,0.f,0.f);
    #pragma unroll 2
    for (int idx = beg; idx < end; idx++){
        int row = g_srow[idx], src = g_ssrc[idx];
        float4 a = a4[row];
        float ah = (h==0) ? a.x : (h==1) ? a.y : (h==2) ? a.z : a.w;
        float4 xv = *(const float4*)&g_xl[(size_t)src*HC + cbase];
        accv.x += ah*xv.x; accv.y += ah*xv.y; accv.z += ah*xv.z; accv.w += ah*xv.w;
    }
    {
        float ah = (h==0) ? asl0 : (h==1) ? asl1 : (h==2) ? asl2 : asl3;
        float4 xv = *(const float4*)&g_xl[(size_t)n*HC + cbase];
        accv.x += ah*xv.x; accv.y += ah*xv.y; accv.z += ah*xv.z; accv.w += ah*xv.w;
    }

    float4 xres = *(const float4*)&x[(size_t)n*DD + cbase];
    float4 gb4  = *(const float4*)&gbias[cbase];
    float v0 = accv.x + xres.x + gb4.x;
    float v1 = accv.y + xres.y + gb4.y;
    float v2 = accv.z + xres.z + gb4.z;
    float v3 = accv.w + xres.w + gb4.w;
    float s = v0+v1+v2+v3;
    #pragma unroll
    for (int o = 16; o; o >>= 1) s += __shfl_xor_sync(0xffffffffu, s, o);
    float mu = s * (1.f/128.f);
    float q = (v0-mu)*(v0-mu) + (v1-mu)*(v1-mu) + (v2-mu)*(v2-mu) + (v3-mu)*(v3-mu);
    #pragma unroll
    for (int o = 16; o; o >>= 1) q += __shfl_xor_sync(0xffffffffu, q, o);
    float rstd = rsqrtf(q*(1.f/128.f) + 1e-5f);
    float4 g14 = *(const float4*)&g1[cbase];
    float4 b14 = *(const float4*)&b1[cbase];
    *(float4*)&g_h[(size_t)n*DD + cbase] = make_float4(
        (v0-mu)*rstd*g14.x + b14.x, (v1-mu)*rstd*g14.y + b14.y,
        (v2-mu)*rstd*g14.z + b14.z, (v3-mu)*rstd*g14.w + b14.w);
}

// ---------------- launch ----------------
extern "C" void kernel_launch(void* const* d_in, const int* in_sizes, int n_in,
                              void* d_out, int out_size) {
    const float* x   = (const float*)d_in[0];
    const int*   ei  = (const int*)  d_in[1];
    const float* ea  = (const float*)d_in[2];
    const float* Wl  = (const float*)d_in[3];
    const float* bl  = (const float*)d_in[4];
    const float* Wr  = (const float*)d_in[5];
    const float* br  = (const float*)d_in[6];
    const float* We  = (const float*)d_in[7];
    const float* att = (const float*)d_in[8];
    const float* gb  = (const float*)d_in[9];
    const float* g1  = (const float*)d_in[10];
    const float* b1  = (const float*)d_in[11];
    const float* g2  = (const float*)d_in[12];
    const float* b2  = (const float*)d_in[13];
    const float* W1  = (const float*)d_in[14];
    const float* W2  = (const float*)d_in[15];

    float* out    = (float*)d_out;
    float* out_ei = out + (size_t)NN*DD;
    float* alpha  = out + (size_t)NN*DD + 2*(size_t)EN;

    cudaFuncSetAttribute(k_elogits_hmma, cudaFuncAttributeMaxDynamicSharedMemorySize, EL_SMEM_BYTES);
    cudaFuncSetAttribute(hgemm_wide<0,0,true,false>,  cudaFuncAttributeMaxDynamicSharedMemorySize, WIDE_SMEM_BYTES);
    cudaFuncSetAttribute(hgemm_wide<6,7,false,true>,  cudaFuncAttributeMaxDynamicSharedMemorySize, WIDE_SMEM_BYTES);
    cudaFuncSetAttribute(hgemm<7,true>,               cudaFuncAttributeMaxDynamicSharedMemorySize, EL_SMEM_BYTES);

    const int T = 256;
    int rowsN64 = (NN + 63)/64;       // 782
    int rowsN = (NN + 127)/128;       // 391
    k_wsplit<<<(WPAIRS + T-1)/T, T>>>(We, Wl, Wr, W1, W2);                                    // 0
    k_init<<<(EN + T-1)/T, T>>>(out_ei, ei);                                                  // 1
    k_scan1<<<SCAN_NBLK, 256>>>();                                                            // 2
    hgemm_wide<0,0,true,false><<<rowsN64, 256, WIDE_SMEM_BYTES>>>(x, bl, br, NN, 128, WOFF_WL, WOFF_WR);  // 3 <- profiled
    k_scan2<<<1, 256>>>();                                                                    // 4
    k_scan3<<<SCAN_NBLK, 256>>>();                                                            // 5
    k_scatter<<<(EE + T-1)/T, T>>>(ei);                                                       // 6
    k_loopattr<<<(NN*32 + T-1)/T, T>>>(ea);                                                   // 7

    k_elogits_hmma<<<EL_GRID, 256, EL_SMEM_BYTES>>>(ei, ea, att, alpha);
    k_smagg<<<(NN*32 + T-1)/T, T>>>(x, gb, g1, b1, alpha);

    hgemm_wide<6,7,false,true><<<rowsN64, 256, WIDE_SMEM_BYTES>>>(nullptr, nullptr, nullptr, NN, 128, WOFF_W1, WOFF_W1 + 128*128);
    hgemm<7,true><<<dim3(1, rowsN), 256, EL_SMEM_BYTES>>>(nullptr, g2, b2, out, NN, 128, 256, WOFF_W2);
}

// round 17
// speedup vs baseline: 1.1970x; 1.1970x over previous
#include <cuda_runtime.h>
#include <cuda_bf16.h>
#include <math.h>
#include <stdint.h>

#define NN 50000
#define EE 640000
#define DD 128
#define EDIM 64
#define HH 4
#define HC 128
#define EN (EE+NN)

#define WOFF_WE 0
#define WOFF_WL 8192
#define WOFF_WR 24576
#define WOFF_W1 40960
#define WOFF_W2 73728
#define WTOTAL  106496
#define WPAIRS  (WTOTAL/2)

#define SCAN_NBLK ((NN + 255)/256)   // 196
#define EL_NTILES ((EN + 127)/128)   // 5391
#define EL_GRID 296                  // 2 CTAs per SM

// ---------------- scratch (device globals; no allocation) ----------------
__device__ float g_xl[NN*HC];
__device__ float g_xr[NN*HC];
__device__ float g_loop[NN*EDIM];
__device__ float g_h[NN*DD];
__device__ float g_mid[NN*2*DD];
__device__ uint32_t g_w16h[WPAIRS];
__device__ uint32_t g_w16l[WPAIRS];
__device__ int   g_cnt[NN];
__device__ int   g_cur[NN];
__device__ int   g_off[NN+1];
__device__ int   g_bsum[SCAN_NBLK];
__device__ int   g_boff[SCAN_NBLK];
__device__ int   g_srow[EE];
__device__ int   g_ssrc[EE];

// device-global router: device globals must NEVER cross the launch boundary as args
template<int B> __device__ __forceinline__ float* bufsel(const float* ext){
    if constexpr (B==0) return const_cast<float*>(ext);
    else if constexpr (B==1) return g_xl;
    else if constexpr (B==2) return g_xr;
    else if constexpr (B==6) return g_h;
    else return g_mid;
}

// ---------------- bf16 split helpers ----------------
__device__ __forceinline__ uint32_t bf16x2_of(float lo_elem, float hi_elem){
    uint32_t r; asm("cvt.rn.bf16x2.f32 %0, %1, %2;" : "=r"(r) : "f"(hi_elem), "f"(lo_elem)); return r;
}
__device__ __forceinline__ float2 bf16x2_back(uint32_t p){
    return make_float2(__uint_as_float(p << 16), __uint_as_float(p & 0xffff0000u));
}
__device__ __forceinline__ void split2(float x, float y, uint32_t& h, uint32_t& l){
    h = bf16x2_of(x, y);
    float2 hb = bf16x2_back(h);
    l = bf16x2_of(x - hb.x, y - hb.y);
}

__device__ __forceinline__ uint32_t smem_u32(const void* p){
    uint32_t a;
    asm("{ .reg .u64 t; cvta.to.shared.u64 t, %1; cvt.u32.u64 %0, t; }" : "=r"(a) : "l"(p));
    return a;
}

__device__ __forceinline__ void ldsm_x4(uint32_t* r, uint32_t addr){
    asm volatile("ldmatrix.sync.aligned.m8n8.x4.shared.b16 {%0,%1,%2,%3}, [%4];"
        : "=r"(r[0]), "=r"(r[1]), "=r"(r[2]), "=r"(r[3]) : "r"(addr));
}
__device__ __forceinline__ void mma16816(float* c, const uint32_t* a, uint32_t b0, uint32_t b1){
    asm volatile("mma.sync.aligned.m16n8k16.row.col.f32.bf16.bf16.f32 "
        "{%0,%1,%2,%3}, {%4,%5,%6,%7}, {%8,%9}, {%0,%1,%2,%3};"
        : "+f"(c[0]), "+f"(c[1]), "+f"(c[2]), "+f"(c[3])
        : "r"(a[0]), "r"(a[1]), "r"(a[2]), "r"(a[3]), "r"(b0), "r"(b1));
}

#define EL_STRIDE 72
#define EL_BUF (128*EL_STRIDE*2)          // 18432 B per buffer
#define EL_SMEM_BYTES (4*EL_BUF)          // 73728 B

// ---------------- weight pre-split + zero counters ----------------
__global__ void k_wsplit(const float* __restrict__ We, const float* __restrict__ Wl,
                         const float* __restrict__ Wr, const float* __restrict__ W1,
                         const float* __restrict__ W2){
    int p = blockIdx.x*blockDim.x + threadIdx.x;
    if (p < NN) g_cnt[p] = 0;
    if (p >= WPAIRS) return;
    int e = p*2;
    const float* src; int base;
    if (e < WOFF_WL)      { src = We; base = WOFF_WE; }
    else if (e < WOFF_WR) { src = Wl; base = WOFF_WL; }
    else if (e < WOFF_W1) { src = Wr; base = WOFF_WR; }
    else if (e < WOFF_W2) { src = W1; base = WOFF_W1; }
    else                  { src = W2; base = WOFF_W2; }
    float2 v = *(const float2*)&src[e - base];
    uint32_t h, l; split2(v.x, v.y, h, l);
    g_w16h[p] = h; g_w16l[p] = l;
}

// ---------------- init: ei_sl output + degree count ----------------
__global__ void k_init(float* __restrict__ out_ei, const int* __restrict__ ei){
    int i = blockIdx.x*blockDim.x + threadIdx.x;
    if (i < EN){
        int s = (i < EE) ? ei[i]     : (i-EE);
        int d = (i < EE) ? ei[EE+i]  : (i-EE);
        out_ei[i]    = (float)s;
        out_ei[EN+i] = (float)d;
        if (i < EE) atomicAdd(&g_cnt[d], 1);
    }
}

// 3-phase parallel scan
__global__ void k_scan1(){
    __shared__ int sp[8];
    int b = blockIdx.x, t = threadIdx.x;
    int idx = b*256 + t;
    int v = (idx < NN) ? g_cnt[idx] : 0;
    int s = v;
    #pragma unroll
    for (int o = 16; o; o >>= 1) s += __shfl_xor_sync(0xffffffffu, s, o);
    if ((t & 31) == 0) sp[t >> 5] = s;
    __syncthreads();
    if (t == 0){
        int tot = 0;
        #pragma unroll
        for (int i = 0; i < 8; i++) tot += sp[i];
        g_bsum[b] = tot;
    }
}

__global__ void k_scan2(){
    __shared__ int buf[SCAN_NBLK];
    int t = threadIdx.x;
    int v = (t < SCAN_NBLK) ? g_bsum[t] : 0;
    if (t < SCAN_NBLK) buf[t] = v;
    __syncthreads();
    for (int off = 1; off < SCAN_NBLK; off <<= 1){
        int add = (t < SCAN_NBLK && t >= off) ? buf[t-off] : 0;
        __syncthreads();
        if (t < SCAN_NBLK) buf[t] += add;
        __syncthreads();
    }
    if (t < SCAN_NBLK) g_boff[t] = buf[t] - v;
}

__global__ void k_scan3(){
    __shared__ int buf[256];
    int b = blockIdx.x, t = threadIdx.x;
    int idx = b*256 + t;
    int v = (idx < NN) ? g_cnt[idx] : 0;
    buf[t] = v;
    __syncthreads();
    for (int off = 1; off < 256; off <<= 1){
        int add = (t >= off) ? buf[t-off] : 0;
        __syncthreads();
        buf[t] += add;
        __syncthreads();
    }
    int ex = g_boff[b] + buf[t] - v;
    if (idx < NN){
        g_off[idx] = ex;
        g_cur[idx] = ex;
        if (idx == NN-1) g_off[NN] = ex + v;
    }
}

__global__ void k_scatter(const int* __restrict__ ei){
    int i = blockIdx.x*blockDim.x + threadIdx.x;
    if (i >= EE) return;
    int d = ei[EE+i];
    int p = atomicAdd(&g_cur[d], 1);
    g_srow[p] = i;
    g_ssrc[p] = ei[i];
}

// ---------------- loop attr: CSR gather mean (warp per node, float2) ----------------
__global__ void k_loopattr(const float* __restrict__ ea){
    int t = blockIdx.x*blockDim.x + threadIdx.x;
    int n = t >> 5, lane = t & 31;
    if (n >= NN) return;
    int beg = g_off[n], end = g_off[n+1];
    float a0 = 0.f, a1 = 0.f;
    #pragma unroll 4
    for (int idx = beg; idx < end; idx++){
        int row = g_srow[idx];
        float2 v = *(const float2*)&ea[(size_t)row*EDIM + lane*2];
        a0 += v.x; a1 += v.y;
    }
    float inv = 1.f / fmaxf((float)(end-beg), 1.f);
    *(float2*)&g_loop[(size_t)n*EDIM + lane*2] = make_float2(a0*inv, a1*inv);
}

// ---------------- HMMA GEMM: C = A * B^T (+bias)(+gelu)(+residual-LN) ----------------
// 128x128 tile, K-loop BK=64, warp = 16M x 128N (settled optimum; do not modify)
template<int ABUF, int CBUF, bool BIAS, bool GELU, bool LN2>
__global__ __launch_bounds__(256) void hgemm(
    const float* __restrict__ Aext, const float* __restrict__ bias,
    const float* __restrict__ gam, const float* __restrict__ bet,
    float* __restrict__ Cext, int M, int Ncol, int K, int woff)
{
    const float* A = bufsel<ABUF>(Aext);
    float* C = bufsel<CBUF>((const float*)Cext);
    extern __shared__ __align__(16) uint8_t dynsmem[];
    uint16_t* Ah = (uint16_t*)(dynsmem);
    uint16_t* Al = (uint16_t*)(dynsmem + EL_BUF);
    uint16_t* Bh = (uint16_t*)(dynsmem + 2*EL_BUF);
    uint16_t* Bl = (uint16_t*)(dynsmem + 3*EL_BUF);

    int tid = threadIdx.x;
    int w = tid >> 5, lane = tid & 31;
    int row0 = blockIdx.y * 128, col0 = blockIdx.x * 128;
    int m0 = w*16;

    float acc[16][4];
    #pragma unroll
    for (int j=0;j<16;j++){ acc[j][0]=0.f; acc[j][1]=0.f; acc[j][2]=0.f; acc[j][3]=0.f; }

    int crow = tid >> 1, chalf = tid & 1;
    int cb = chalf*32;
    int gm = row0 + crow;

    int arow_l = m0 + (lane & 15);
    int akoff  = (lane >> 4) * 8;
    uint32_t addrAh = smem_u32(Ah) + (arow_l*EL_STRIDE + akoff)*2;
    uint32_t addrAl = smem_u32(Al) + (arow_l*EL_STRIDE + akoff)*2;
    int brow_l = (lane & 7) + ((lane >> 4) << 3);
    int bkoff  = ((lane >> 3) & 1) * 8;
    uint32_t addrBh = smem_u32(Bh) + (brow_l*EL_STRIDE + bkoff)*2;
    uint32_t addrBl = smem_u32(Bl) + (brow_l*EL_STRIDE + bkoff)*2;

    for (int k0 = 0; k0 < K; k0 += 64){
        {
            const float* arow = (gm < M) ? &A[(size_t)gm*K + k0 + cb] : nullptr;
            #pragma unroll
            for (int q = 0; q < 8; q++){
                int col = cb + q*4;
                uint32_t h0, l0, h1, l1;
                if (!arow){ h0=l0=h1=l1=0u; }
                else {
                    float4 v = *(const float4*)&arow[q*4];
                    split2(v.x, v.y, h0, l0);
                    split2(v.z, v.w, h1, l1);
                }
                *(uint2*)&Ah[crow*EL_STRIDE + col] = make_uint2(h0, h1);
                *(uint2*)&Al[crow*EL_STRIDE + col] = make_uint2(l0, l1);
            }
        }
        {
            int belem = woff + (col0+crow)*K + k0 + cb;
            #pragma unroll
            for (int q = 0; q < 8; q++){
                int col = cb + q*4;
                int pidx = (belem + q*4) >> 1;
                *(uint2*)&Bh[crow*EL_STRIDE + col] = *(const uint2*)&g_w16h[pidx];
                *(uint2*)&Bl[crow*EL_STRIDE + col] = *(const uint2*)&g_w16l[pidx];
            }
        }
        __syncthreads();
        #pragma unroll
        for (int kk = 0; kk < 4; kk++){
            uint32_t kofs = (kk*16)*2;
            uint32_t ah[4], al[4];
            ldsm_x4(ah, addrAh + kofs);
            ldsm_x4(al, addrAl + kofs);
            #pragma unroll
            for (int jj = 0; jj < 8; jj++){
                uint32_t bofs = (jj*16*EL_STRIDE)*2 + kofs;
                uint32_t bh[4], bl[4];
                ldsm_x4(bh, addrBh + bofs);
                ldsm_x4(bl, addrBl + bofs);
                mma16816(acc[2*jj],   ah, bh[0], bh[1]);
                mma16816(acc[2*jj+1], ah, bh[2], bh[3]);
                mma16816(acc[2*jj],   ah, bl[0], bl[1]);
                mma16816(acc[2*jj+1], ah, bl[2], bl[3]);
                mma16816(acc[2*jj],   al, bh[0], bh[1]);
                mma16816(acc[2*jj+1], al, bh[2], bh[3]);
            }
        }
        __syncthreads();
    }

    int qid = lane >> 2;
    int r0 = row0 + m0 + qid, r1 = r0 + 8;
    int cbase = (lane & 3)*2;

    if (LN2){
        #pragma unroll
        for (int j = 0; j < 16; j++){
            int c = col0 + j*8 + cbase;
            if (r0 < M){
                float2 hv = *(const float2*)&g_h[(size_t)r0*Ncol + c];
                acc[j][0] += hv.x; acc[j][1] += hv.y;
            }
            if (r1 < M){
                float2 hv = *(const float2*)&g_h[(size_t)r1*Ncol + c];
                acc[j][2] += hv.x; acc[j][3] += hv.y;
            }
        }
        float s0 = 0.f, s1 = 0.f;
        #pragma unroll
        for (int j = 0; j < 16; j++){ s0 += acc[j][0] + acc[j][1]; s1 += acc[j][2] + acc[j][3]; }
        s0 += __shfl_xor_sync(0xffffffffu, s0, 1); s0 += __shfl_xor_sync(0xffffffffu, s0, 2);
        s1 += __shfl_xor_sync(0xffffffffu, s1, 1); s1 += __shfl_xor_sync(0xffffffffu, s1, 2);
        float mu0 = s0 * (1.f/128.f), mu1 = s1 * (1.f/128.f);
        float q0 = 0.f, q1 = 0.f;
        #pragma unroll
        for (int j = 0; j < 16; j++){
            float d;
            d = acc[j][0]-mu0; q0 += d*d;
            d = acc[j][1]-mu0; q0 += d*d;
            d = acc[j][2]-mu1; q1 += d*d;
            d = acc[j][3]-mu1; q1 += d*d;
        }
        q0 += __shfl_xor_sync(0xffffffffu, q0, 1); q0 += __shfl_xor_sync(0xffffffffu, q0, 2);
        q1 += __shfl_xor_sync(0xffffffffu, q1, 1); q1 += __shfl_xor_sync(0xffffffffu, q1, 2);
        float rs0 = rsqrtf(q0*(1.f/128.f) + 1e-5f);
        float rs1 = rsqrtf(q1*(1.f/128.f) + 1e-5f);
        #pragma unroll
        for (int j = 0; j < 16; j++){
            int c = col0 + j*8 + cbase;
            float2 gv = *(const float2*)&gam[c];
            float2 bv = *(const float2*)&bet[c];
            if (r0 < M)
                *(float2*)&C[(size_t)r0*Ncol + c] = make_float2(
                    (acc[j][0]-mu0)*rs0*gv.x + bv.x, (acc[j][1]-mu0)*rs0*gv.y + bv.y);
            if (r1 < M)
                *(float2*)&C[(size_t)r1*Ncol + c] = make_float2(
                    (acc[j][2]-mu1)*rs1*gv.x + bv.x, (acc[j][3]-mu1)*rs1*gv.y + bv.y);
        }
    } else {
        #pragma unroll
        for (int j = 0; j < 16; j++){
            int c = col0 + j*8 + cbase;
            float v0 = acc[j][0], v1 = acc[j][1], v2 = acc[j][2], v3 = acc[j][3];
            if (BIAS){
                float2 bv = *(const float2*)&bias[c];
                v0 += bv.x; v1 += bv.y; v2 += bv.x; v3 += bv.y;
            }
            if (GELU){
                v0 = 0.5f*v0*(1.f + erff(v0*0.70710678118654752f));
                v1 = 0.5f*v1*(1.f + erff(v1*0.70710678118654752f));
                v2 = 0.5f*v2*(1.f + erff(v2*0.70710678118654752f));
                v3 = 0.5f*v3*(1.f + erff(v3*0.70710678118654752f));
            }
            if (r0 < M) *(float2*)&C[(size_t)r0*Ncol + c] = make_float2(v0, v1);
            if (r1 < M) *(float2*)&C[(size_t)r1*Ncol + c] = make_float2(v2, v3);
        }
    }
}

// ---------------- fused e-projection + logits: PERSISTENT, We staged once ----------------
__global__ __launch_bounds__(256) void k_elogits_hmma(
    const int* __restrict__ ei, const float* __restrict__ ea,
    const float* __restrict__ att, float* __restrict__ alpha)
{
    extern __shared__ __align__(16) uint8_t dynsmem[];
    __shared__ int s_src[128], s_dst[128];
    __shared__ float s_att[128];

    uint16_t* Ah = (uint16_t*)(dynsmem);
    uint16_t* Al = (uint16_t*)(dynsmem + EL_BUF);
    uint16_t* Bh = (uint16_t*)(dynsmem + 2*EL_BUF);
    uint16_t* Bl = (uint16_t*)(dynsmem + 3*EL_BUF);

    int tid = threadIdx.x;
    int w = tid >> 5, lane = tid & 31;

    if (tid < 128) s_att[tid] = att[tid];
    {
        int row = tid >> 1, half = tid & 1;
        int cb = half*32;
        int belem = row*EDIM + cb;
        #pragma unroll
        for (int q = 0; q < 8; q++){
            int col = cb + q*4;
            int pidx = (belem + q*4) >> 1;
            *(uint2*)&Bh[row*EL_STRIDE + col] = *(const uint2*)&g_w16h[pidx];
            *(uint2*)&Bl[row*EL_STRIDE + col] = *(const uint2*)&g_w16l[pidx];
        }
    }

    int m0 = w*16;
    int arow_l = m0 + (lane & 15);
    int akoff  = (lane >> 4) * 8;
    uint32_t addrAh = smem_u32(Ah) + (arow_l*EL_STRIDE + akoff)*2;
    uint32_t addrAl = smem_u32(Al) + (arow_l*EL_STRIDE + akoff)*2;
    int brow_l = (lane & 7) + ((lane >> 4) << 3);
    int bkoff  = ((lane >> 3) & 1) * 8;
    uint32_t addrBh = smem_u32(Bh) + (brow_l*EL_STRIDE + bkoff)*2;
    uint32_t addrBl = smem_u32(Bl) + (brow_l*EL_STRIDE + bkoff)*2;

    int crow = tid >> 1, chalf = tid & 1;
    int ccb = chalf*32;

    for (int tile = blockIdx.x; tile < EL_NTILES; tile += EL_GRID){
        int row0 = tile * 128;

        if (tid < 128){
            int e = row0 + tid;
            int s, d;
            if (e < EE){ s = ei[e]; d = ei[EE+e]; }
            else if (e < EN){ s = e-EE; d = e-EE; }
            else { s = 0; d = 0; }
            s_src[tid] = s; s_dst[tid] = d;
        }
        {
            int eg = row0 + crow;
            const float* arow = nullptr;
            bool zero = false;
            if (eg < EE)      arow = &ea[(size_t)eg*EDIM + ccb];
            else if (eg < EN) arow = &g_loop[(size_t)(eg-EE)*EDIM + ccb];
            else              zero = true;
            #pragma unroll
            for (int q = 0; q < 8; q++){
                int col = ccb + q*4;
                uint32_t h0, l0, h1, l1;
                if (zero){ h0=l0=h1=l1=0u; }
                else {
                    float4 v = *(const float4*)&arow[q*4];
                    split2(v.x, v.y, h0, l0);
                    split2(v.z, v.w, h1, l1);
                }
                *(uint2*)&Ah[crow*EL_STRIDE + col] = make_uint2(h0, h1);
                *(uint2*)&Al[crow*EL_STRIDE + col] = make_uint2(l0, l1);
            }
        }
        __syncthreads();

        float acc[16][4];
        #pragma unroll
        for (int j=0;j<16;j++){ acc[j][0]=0.f; acc[j][1]=0.f; acc[j][2]=0.f; acc[j][3]=0.f; }

        #pragma unroll
        for (int kk = 0; kk < 4; kk++){
            uint32_t kofs = (kk*16)*2;
            uint32_t ah[4], al[4];
            ldsm_x4(ah, addrAh + kofs);
            ldsm_x4(al, addrAl + kofs);
            #pragma unroll
            for (int jj = 0; jj < 8; jj++){
                uint32_t bofs = (jj*16*EL_STRIDE)*2 + kofs;
                uint32_t bh[4], bl[4];
                ldsm_x4(bh, addrBh + bofs);
                ldsm_x4(bl, addrBl + bofs);
                mma16816(acc[2*jj],   ah, bh[0], bh[1]);
                mma16816(acc[2*jj+1], ah, bh[2], bh[3]);
                mma16816(acc[2*jj],   ah, bl[0], bl[1]);
                mma16816(acc[2*jj+1], ah, bl[2], bl[3]);
                mma16816(acc[2*jj],   al, bh[0], bh[1]);
                mma16816(acc[2*jj+1], al, bh[2], bh[3]);
            }
        }

        int qid = lane >> 2;
        int r0 = m0 + qid, r1 = r0 + 8;
        int eg0 = row0 + r0, eg1 = row0 + r1;
        int sA = s_src[r0], dA = s_dst[r0];
        int sB = s_src[r1], dB = s_dst[r1];
        const float* xlA = g_xl + (size_t)sA*HC;
        const float* xrA = g_xr + (size_t)dA*HC;
        const float* xlB = g_xl + (size_t)sB*HC;
        const float* xrB = g_xr + (size_t)dB*HC;
        int cbase = (lane & 3)*2;
        float p0[4] = {0.f,0.f,0.f,0.f};
        float p1[4] = {0.f,0.f,0.f,0.f};
        #pragma unroll
        for (int j = 0; j < 16; j++){
            int c = j*8 + cbase;
            int head = j >> 2;
            float2 xl0 = *(const float2*)&xlA[c];
            float2 xr0 = *(const float2*)&xrA[c];
            float2 xl1 = *(const float2*)&xlB[c];
            float2 xr1 = *(const float2*)&xrB[c];
            float a0 = s_att[c], a1 = s_att[c+1];
            float v;
            v = acc[j][0] + xl0.x + xr0.x; v = (v>0.f)?v:0.2f*v; p0[head] += v*a0;
            v = acc[j][1] + xl0.y + xr0.y; v = (v>0.f)?v:0.2f*v; p0[head] += v*a1;
            v = acc[j][2] + xl1.x + xr1.x; v = (v>0.f)?v:0.2f*v; p1[head] += v*a0;
            v = acc[j][3] + xl1.y + xr1.y; v = (v>0.f)?v:0.2f*v; p1[head] += v*a1;
        }
        #pragma unroll
        for (int o = 1; o <= 2; o <<= 1){
            #pragma unroll
            for (int hh = 0; hh < 4; hh++){
                p0[hh] += __shfl_xor_sync(0xffffffffu, p0[hh], o);
                p1[hh] += __shfl_xor_sync(0xffffffffu, p1[hh], o);
            }
        }
        if ((lane & 3) == 0){
            if (eg0 < EN) *(float4*)&alpha[(size_t)eg0*4] = make_float4(p0[0], p0[1], p0[2], p0[3]);
            if (eg1 < EN) *(float4*)&alpha[(size_t)eg1*4] = make_float4(p1[0], p1[1], p1[2], p1[3]);
        }
        __syncthreads();
    }
}

// ---------------- online segment softmax + aggregate + residual + LN1 ----------------
__device__ __forceinline__ void online_upd(float l, float& m, float& s){
    if (l > m){ s = s*__expf(m-l) + 1.f; m = l; }
    else s += __expf(l-m);
}
__device__ __forceinline__ void online_merge(float om, float os, float& m, float& s){
    float nm = fmaxf(m, om);
    s = s*__expf(m-nm) + os*__expf(om-nm);
    m = nm;
}

__global__ void k_smagg(const float* __restrict__ x, const float* __restrict__ gbias,
                        const float* __restrict__ g1, const float* __restrict__ b1,
                        float* __restrict__ alpha)
{
    int t = blockIdx.x*blockDim.x + threadIdx.x;
    int n = t >> 5, lane = t & 31;
    if (n >= NN) return;
    int beg = g_off[n], end = g_off[n+1];
    float4* a4 = (float4*)alpha;

    float4 lsl = a4[EE+n];
    const float NEGBIG = -1e30f;
    float m0=NEGBIG,m1=NEGBIG,m2=NEGBIG,m3=NEGBIG;
    float s0=0.f,s1=0.f,s2=0.f,s3=0.f;
    for (int idx = beg + lane; idx < end; idx += 32){
        float4 l = a4[g_srow[idx]];
        online_upd(l.x, m0, s0); online_upd(l.y, m1, s1);
        online_upd(l.z, m2, s2); online_upd(l.w, m3, s3);
    }
    #pragma unroll
    for (int o = 16; o; o >>= 1){
        float om, os;
        om = __shfl_xor_sync(0xffffffffu, m0, o); os = __shfl_xor_sync(0xffffffffu, s0, o); online_merge(om, os, m0, s0);
        om = __shfl_xor_sync(0xffffffffu, m1, o); os = __shfl_xor_sync(0xffffffffu, s1, o); online_merge(om, os, m1, s1);
        om = __shfl_xor_sync(0xffffffffu, m2, o); os = __shfl_xor_sync(0xffffffffu, s2, o); online_merge(om, os, m2, s2);
        om = __shfl_xor_sync(0xffffffffu, m3, o); os = __shfl_xor_sync(0xffffffffu, s3, o); online_merge(om, os, m3, s3);
    }
    online_upd(lsl.x, m0, s0); online_upd(lsl.y, m1, s1);
    online_upd(lsl.z, m2, s2); online_upd(lsl.w, m3, s3);

    float i0 = 1.f/s0, i1 = 1.f/s1, i2 = 1.f/s2, i3 = 1.f/s3;
    float asl0 = __expf(lsl.x - m0)*i0, asl1 = __expf(lsl.y - m1)*i1;
    float asl2 = __expf(lsl.z - m2)*i2, asl3 = __expf(lsl.w - m3)*i3;
    if (lane == 0) a4[EE+n] = make_float4(asl0, asl1, asl2, asl3);
    for (int idx = beg + lane; idx < end; idx += 32){
        int row = g_srow[idx];
        float4 l = a4[row];
        a4[row] = make_float4(__expf(l.x - m0)*i0, __expf(l.y - m1)*i1,
                              __expf(l.z - m2)*i2, __expf(l.w - m3)*i3);
    }
    __syncwarp();

    int cbase = lane*4;
    int h = lane >> 3;
    float4 accv = make_float4(0.f,0.f,0.f,0.f);
    #pragma unroll 4
    for (int idx = beg; idx < end; idx++){
        int row = g_srow[idx], src = g_ssrc[idx];
        float4 a = a4[row];
        float ah = (h==0) ? a.x : (h==1) ? a.y : (h==2) ? a.z : a.w;
        float4 xv = *(const float4*)&g_xl[(size_t)src*HC + cbase];
        accv.x += ah*xv.x; accv.y += ah*xv.y; accv.z += ah*xv.z; accv.w += ah*xv.w;
    }
    {
        float ah = (h==0) ? asl0 : (h==1) ? asl1 : (h==2) ? asl2 : asl3;
        float4 xv = *(const float4*)&g_xl[(size_t)n*HC + cbase];
        accv.x += ah*xv.x; accv.y += ah*xv.y; accv.z += ah*xv.z; accv.w += ah*xv.w;
    }

    float4 xres = *(const float4*)&x[(size_t)n*DD + cbase];
    float4 gb4  = *(const float4*)&gbias[cbase];
    float v0 = accv.x + xres.x + gb4.x;
    float v1 = accv.y + xres.y + gb4.y;
    float v2 = accv.z + xres.z + gb4.z;
    float v3 = accv.w + xres.w + gb4.w;
    float s = v0+v1+v2+v3;
    #pragma unroll
    for (int o = 16; o; o >>= 1) s += __shfl_xor_sync(0xffffffffu, s, o);
    float mu = s * (1.f/128.f);
    float q = (v0-mu)*(v0-mu) + (v1-mu)*(v1-mu) + (v2-mu)*(v2-mu) + (v3-mu)*(v3-mu);
    #pragma unroll
    for (int o = 16; o; o >>= 1) q += __shfl_xor_sync(0xffffffffu, q, o);
    float rstd = rsqrtf(q*(1.f/128.f) + 1e-5f);
    float4 g14 = *(const float4*)&g1[cbase];
    float4 b14 = *(const float4*)&b1[cbase];
    *(float4*)&g_h[(size_t)n*DD + cbase] = make_float4(
        (v0-mu)*rstd*g14.x + b14.x, (v1-mu)*rstd*g14.y + b14.y,
        (v2-mu)*rstd*g14.z + b14.z, (v3-mu)*rstd*g14.w + b14.w);
}

// ---------------- launch ----------------
extern "C" void kernel_launch(void* const* d_in, const int* in_sizes, int n_in,
                              void* d_out, int out_size) {
    const float* x   = (const float*)d_in[0];
    const int*   ei  = (const int*)  d_in[1];
    const float* ea  = (const float*)d_in[2];
    const float* Wl  = (const float*)d_in[3];
    const float* bl  = (const float*)d_in[4];
    const float* Wr  = (const float*)d_in[5];
    const float* br  = (const float*)d_in[6];
    const float* We  = (const float*)d_in[7];
    const float* att = (const float*)d_in[8];
    const float* gb  = (const float*)d_in[9];
    const float* g1  = (const float*)d_in[10];
    const float* b1  = (const float*)d_in[11];
    const float* g2  = (const float*)d_in[12];
    const float* b2  = (const float*)d_in[13];
    const float* W1  = (const float*)d_in[14];
    const float* W2  = (const float*)d_in[15];

    float* out    = (float*)d_out;
    float* out_ei = out + (size_t)NN*DD;
    float* alpha  = out + (size_t)NN*DD + 2*(size_t)EN;

    cudaFuncSetAttribute(k_elogits_hmma, cudaFuncAttributeMaxDynamicSharedMemorySize, EL_SMEM_BYTES);
    cudaFuncSetAttribute(hgemm<0,1,true,false,false>,  cudaFuncAttributeMaxDynamicSharedMemorySize, EL_SMEM_BYTES);
    cudaFuncSetAttribute(hgemm<0,2,true,false,false>,  cudaFuncAttributeMaxDynamicSharedMemorySize, EL_SMEM_BYTES);
    cudaFuncSetAttribute(hgemm<6,7,false,true,false>,  cudaFuncAttributeMaxDynamicSharedMemorySize, EL_SMEM_BYTES);
    cudaFuncSetAttribute(hgemm<7,0,false,false,true>,  cudaFuncAttributeMaxDynamicSharedMemorySize, EL_SMEM_BYTES);

    // side stream + events, created once (host-side objects; identical captured work every call)
    static cudaStream_t s2 = nullptr;
    static cudaEvent_t evF = nullptr, evJ = nullptr;
    if (!s2){
        cudaStreamCreateWithFlags(&s2, cudaStreamNonBlocking);
        cudaEventCreateWithFlags(&evF, cudaEventDisableTiming);
        cudaEventCreateWithFlags(&evJ, cudaEventDisableTiming);
    }

    const int T = 256;
    int rowsN = (NN + 127)/128;

    k_wsplit<<<(WPAIRS + T-1)/T, T>>>(We, Wl, Wr, W1, W2);
    k_init<<<(EN + T-1)/T, T>>>(out_ei, ei);

    // fork: xl/xr projections (tensor) concurrent with CSR build + loopattr (memory)
    cudaEventRecord(evF, 0);
    cudaStreamWaitEvent(s2, evF, 0);
    hgemm<0,1,true,false,false><<<dim3(1, rowsN), 256, EL_SMEM_BYTES, s2>>>(x, bl, nullptr, nullptr, nullptr, NN, 128, 128, WOFF_WL);
    hgemm<0,2,true,false,false><<<dim3(1, rowsN), 256, EL_SMEM_BYTES, s2>>>(x, br, nullptr, nullptr, nullptr, NN, 128, 128, WOFF_WR);
    cudaEventRecord(evJ, s2);

    k_scan1<<<SCAN_NBLK, 256>>>();
    k_scan2<<<1, 256>>>();
    k_scan3<<<SCAN_NBLK, 256>>>();
    k_scatter<<<(EE + T-1)/T, T>>>(ei);
    k_loopattr<<<(NN*32 + T-1)/T, T>>>(ea);

    cudaStreamWaitEvent(0, evJ, 0);   // join before elogits (needs g_xl/g_xr)

    k_elogits_hmma<<<EL_GRID, 256, EL_SMEM_BYTES>>>(ei, ea, att, alpha);
    k_smagg<<<(NN*32 + T-1)/T, T>>>(x, gb, g1, b1, alpha);

    hgemm<6,7,false,true,false><<<dim3(2, rowsN), 256, EL_SMEM_BYTES>>>(nullptr, nullptr, nullptr, nullptr, nullptr, NN, 256, 128, WOFF_W1);
    hgemm<7,0,false,false,true><<<dim3(1, rowsN), 256, EL_SMEM_BYTES>>>(nullptr, nullptr, g2, b2, out, NN, 128, 256, WOFF_W2);
}